// round 8
// baseline (speedup 1.0000x reference)
#include <cuda_runtime.h>
#include <cuda_bf16.h>
#include <cstdint>

static constexpr int NN = 100000;   // nodes
static constexpr int D  = 64;       // feature dim
static constexpr int NE = 1000000;  // edges
static constexpr int C0 = 50048;    // chunk split (391 tiles of 128)

static constexpr int SCAN_T = 512;
static constexpr int NSCB   = (NN + SCAN_T - 1) / SCAN_T;   // 196

// Scratch (device globals — no allocation allowed)
__device__ float g_h2 [NN * D];   // h = x @ W (unscaled)
__device__ float g_x  [NN * D];   // layer activations
__device__ float g_dinv[NN];
__device__ int   g_degi[NN];      // zero at entry (BSS first call; csr_fill re-zeros)
__device__ int   g_off [NN + 1];
__device__ int   g_cur [NN];
__device__ int   g_scan[NN];
__device__ int   g_bsum[NSCB];
__device__ int   g_csr [NE];      // src ids grouped by dst

// ---------------------------------------------------------------------------
// Per-block int64-vs-int32 detection (JAX may silently downcast edge_index).
__device__ __forceinline__ int block_detect64(const int* __restrict__ w) {
    __shared__ int s_flag;
    if (threadIdx.x == 0) s_flag = 0;
    __syncthreads();
    if (threadIdx.x < 64 && w[2 * threadIdx.x + 1]) atomicOr(&s_flag, 1);
    __syncthreads();
    return s_flag == 0;
}

__device__ __forceinline__ int edge_at(const void* ei, int is64, long long pos) {
    if (is64) return (int)((const long long*)ei)[pos];
    return ((const int*)ei)[pos];
}

__global__ void degi_count(const void* __restrict__ ei) {
    int is64 = block_detect64((const int*)ei);
    int e = blockIdx.x * 256 + threadIdx.x;
    if (e < NE) atomicAdd(&g_degi[edge_at(ei, is64, (long long)NE + e)], 1);
}

// ---- prefix scan ----------------------------------------------------------
__global__ void scan1() {
    __shared__ int s[SCAN_T];
    int i = blockIdx.x * SCAN_T + threadIdx.x;
    int v = (i < NN) ? g_degi[i] : 0;
    s[threadIdx.x] = v;
    __syncthreads();
    #pragma unroll
    for (int off = 1; off < SCAN_T; off <<= 1) {
        int t = (threadIdx.x >= off) ? s[threadIdx.x - off] : 0;
        __syncthreads();
        s[threadIdx.x] += t;
        __syncthreads();
    }
    if (i < NN) g_scan[i] = s[threadIdx.x];
    if (threadIdx.x == SCAN_T - 1) g_bsum[blockIdx.x] = s[threadIdx.x];
}

// Fused: per-block re-scan of block sums + offsets + cursor + dinv.
__global__ void scan23() {
    __shared__ int bs[256];
    int v = (threadIdx.x < NSCB) ? g_bsum[threadIdx.x] : 0;
    bs[threadIdx.x] = v;
    __syncthreads();
    #pragma unroll
    for (int off = 1; off < 256; off <<= 1) {
        int t = (threadIdx.x >= off) ? bs[threadIdx.x - off] : 0;
        __syncthreads();
        bs[threadIdx.x] += t;
        __syncthreads();
    }
    int i = blockIdx.x * 256 + threadIdx.x;
    if (i >= NN) return;
    int b  = i / SCAN_T;
    int di = g_degi[i];
    int incl = g_scan[i] + (b > 0 ? bs[b - 1] : 0);
    g_off[i + 1] = incl;
    if (i == 0) g_off[0] = 0;
    g_cur[i] = incl - di;
    g_dinv[i] = rsqrtf(1.0f + (float)di);
}

// Fill CSR; also re-zero g_degi so the NEXT invocation starts clean.
__global__ void csr_fill(const void* __restrict__ ei) {
    int is64 = block_detect64((const int*)ei);
    int e = blockIdx.x * 256 + threadIdx.x;
    if (e < NN) g_degi[e] = 0;
    if (e >= NE) return;
    int src = edge_at(ei, is64, e);
    int dst = edge_at(ei, is64, (long long)NE + e);
    int pos = atomicAdd(&g_cur[dst], 1);
    g_csr[pos] = src;
}

// ---------------------------------------------------------------------------
// Tensor-core GEMM via mma.sync (sm_80 PTX -> HMMA on sm_103):
//   Y[rows rbase..rend) = X @ W (64x64), bf16 3-pass error compensation.
static constexpr int HSTR  = 72;   // halves per row (64 + 8 pad)
static constexpr int SM_AH = 0;
static constexpr int SM_AL = SM_AH + 128 * HSTR * 2;   // 18432
static constexpr int SM_BH = SM_AL + 128 * HSTR * 2;   // 36864
static constexpr int SM_BL = SM_BH + 64 * HSTR * 2;    // 46080
static constexpr int SM_TOT = SM_BL + 64 * HSTR * 2;   // 55296

__device__ __forceinline__ uint32_t smem_u32(const void* p) {
    uint32_t a;
    asm("{ .reg .u64 t; cvta.to.shared.u64 t, %1; cvt.u32.u64 %0, t; }"
        : "=r"(a) : "l"(p));
    return a;
}
__device__ __forceinline__ void ldsm4(uint32_t& r0, uint32_t& r1, uint32_t& r2,
                                      uint32_t& r3, uint32_t addr) {
    asm volatile("ldmatrix.sync.aligned.m8n8.x4.shared.b16 {%0,%1,%2,%3}, [%4];"
                 : "=r"(r0), "=r"(r1), "=r"(r2), "=r"(r3) : "r"(addr));
}
__device__ __forceinline__ void mma16816(float* c, const uint32_t* a,
                                         uint32_t b0, uint32_t b1) {
    asm volatile(
        "mma.sync.aligned.m16n8k16.row.col.f32.bf16.bf16.f32 "
        "{%0,%1,%2,%3}, {%4,%5,%6,%7}, {%8,%9}, {%0,%1,%2,%3};"
        : "+f"(c[0]), "+f"(c[1]), "+f"(c[2]), "+f"(c[3])
        : "r"(a[0]), "r"(a[1]), "r"(a[2]), "r"(a[3]), "r"(b0), "r"(b1));
}
__device__ __forceinline__ void split_bf16(float x, unsigned short& h, unsigned short& l) {
    __nv_bfloat16 hb = __float2bfloat16(x);
    __nv_bfloat16 lb = __float2bfloat16(x - __bfloat162float(hb));
    h = __bfloat16_as_ushort(hb);
    l = __bfloat16_as_ushort(lb);
}

__global__ void __launch_bounds__(256) gemm_tc(
        const float* __restrict__ X, const float* __restrict__ W,
        const float* __restrict__ bias, float* __restrict__ Y,
        long long rbase, long long rend) {
    extern __shared__ char smem[];
    const int tid  = threadIdx.x;
    const int wid  = tid >> 5;
    const int lane = tid & 31;
    const long long base = rbase + (long long)blockIdx.x * 128;

    // ---- fill A (X tile 128x64 -> hi/lo halves) ----
    #pragma unroll
    for (int i = 0; i < 8; i++) {
        int idx  = tid + i * 256;          // float4 index, 2048 total
        int row  = idx >> 4;
        int k    = (idx & 15) * 4;
        float4 v = make_float4(0.f, 0.f, 0.f, 0.f);
        if (base + row < rend)
            v = ((const float4*)X)[(base + row) * 16 + (k >> 2)];
        unsigned short h0, l0, h1, l1, h2v, l2v, h3, l3;
        split_bf16(v.x, h0, l0); split_bf16(v.y, h1, l1);
        split_bf16(v.z, h2v, l2v); split_bf16(v.w, h3, l3);
        unsigned long long hp = (unsigned long long)h0
            | ((unsigned long long)h1 << 16) | ((unsigned long long)h2v << 32)
            | ((unsigned long long)h3 << 48);
        unsigned long long lp = (unsigned long long)l0
            | ((unsigned long long)l1 << 16) | ((unsigned long long)l2v << 32)
            | ((unsigned long long)l3 << 48);
        uint32_t off = (uint32_t)(row * HSTR + k) * 2;
        *(unsigned long long*)(smem + SM_AH + off) = hp;
        *(unsigned long long*)(smem + SM_AL + off) = lp;
    }
    // ---- fill B (W^T: Bt[n][k] = W[k][n]) ----
    #pragma unroll
    for (int i = 0; i < 16; i++) {
        int idx = tid + i * 256;           // coalesced read of W
        int k = idx >> 6, n = idx & 63;
        unsigned short h, l;
        split_bf16(W[idx], h, l);
        uint32_t off = (uint32_t)(n * HSTR + k) * 2;
        *(unsigned short*)(smem + SM_BH + off) = h;
        *(unsigned short*)(smem + SM_BL + off) = l;
    }
    __syncthreads();

    const uint32_t sb = smem_u32(smem);
    const int r0w = wid * 16;              // warp's 16 output rows

    const int li  = lane >> 3;             // ldmatrix matrix index 0..3
    const int lw  = lane & 7;
    const uint32_t a_off =
        (uint32_t)(((r0w + (li & 1) * 8 + lw) * HSTR + (li >> 1) * 8) * 2);
    const uint32_t b_off =
        (uint32_t)((((li >> 1) * 8 + lw) * HSTR + (li & 1) * 8) * 2);

    float acc[8][4];
    #pragma unroll
    for (int nt = 0; nt < 8; nt++)
        #pragma unroll
        for (int q = 0; q < 4; q++) acc[nt][q] = 0.f;

    const uint32_t aBase[3] = { sb + SM_AH, sb + SM_AH, sb + SM_AL };
    const uint32_t bBase[3] = { sb + SM_BH, sb + SM_BL, sb + SM_BH };

    #pragma unroll
    for (int pass = 0; pass < 3; pass++) {
        #pragma unroll
        for (int kt = 0; kt < 4; kt++) {
            uint32_t a[4];
            ldsm4(a[0], a[1], a[2], a[3], aBase[pass] + a_off + kt * 32);
            #pragma unroll
            for (int ntp = 0; ntp < 4; ntp++) {
                uint32_t b0, b1, b2, b3;
                ldsm4(b0, b1, b2, b3,
                      bBase[pass] + b_off + (uint32_t)(ntp * 16 * HSTR * 2) + kt * 32);
                mma16816(acc[2 * ntp],     a, b0, b1);
                mma16816(acc[2 * ntp + 1], a, b2, b3);
            }
        }
    }

    // ---- epilogue: C frag m16n8 lane mapping ----
    const int rA = r0w + (lane >> 2);
    const int rB = rA + 8;
    long long gA = base + rA, gB = base + rB;
    bool vA = gA < rend, vB = gB < rend;
    #pragma unroll
    for (int nt = 0; nt < 8; nt++) {
        int cg = nt * 8 + (lane & 3) * 2;
        float bx = 0.f, by = 0.f;
        if (bias) { bx = bias[cg]; by = bias[cg + 1]; }
        if (vA) {
            float2 o = make_float2(acc[nt][0] + bx, acc[nt][1] + by);
            *(float2*)&Y[gA * 64 + cg] = o;
        }
        if (vB) {
            float2 o = make_float2(acc[nt][2] + bx, acc[nt][3] + by);
            *(float2*)&Y[gB * 64 + cg] = o;
        }
    }
}

// ---------------------------------------------------------------------------
// CSR gather + fused epilogue (h unscaled), over node range [nbase, nend):
//   x'[v] = relu( dinv[v] * ( dinv[v]*h[v] + sum_src dinv[s]*h[s] ) + b )
__global__ void __launch_bounds__(256) gather_epi(int nbase, int nend,
                                                  const float* __restrict__ bias) {
    int t    = blockIdx.x * 256 + threadIdx.x;
    int node = nbase + (t >> 4);
    if (node >= nend) return;
    int lane = t & 15;

    const float4* __restrict__ h2 = (const float4*)g_h2;
    int beg = g_off[node];
    int end = g_off[node + 1];
    float dv = g_dinv[node];

    float4 hs = h2[node * 16 + lane];
    float4 a;
    a.x = dv * hs.x; a.y = dv * hs.y; a.z = dv * hs.z; a.w = dv * hs.w;

    int e = beg;
    for (; e + 3 < end; e += 4) {
        int s0 = __ldg(&g_csr[e]);
        int s1 = __ldg(&g_csr[e + 1]);
        int s2 = __ldg(&g_csr[e + 2]);
        int s3 = __ldg(&g_csr[e + 3]);
        float d0 = g_dinv[s0], d1 = g_dinv[s1], d2 = g_dinv[s2], d3 = g_dinv[s3];
        float4 v0 = h2[s0 * 16 + lane];
        float4 v1 = h2[s1 * 16 + lane];
        float4 v2 = h2[s2 * 16 + lane];
        float4 v3 = h2[s3 * 16 + lane];
        a.x = fmaf(d0, v0.x, fmaf(d1, v1.x, fmaf(d2, v2.x, fmaf(d3, v3.x, a.x))));
        a.y = fmaf(d0, v0.y, fmaf(d1, v1.y, fmaf(d2, v2.y, fmaf(d3, v3.y, a.y))));
        a.z = fmaf(d0, v0.z, fmaf(d1, v1.z, fmaf(d2, v2.z, fmaf(d3, v3.z, a.z))));
        a.w = fmaf(d0, v0.w, fmaf(d1, v1.w, fmaf(d2, v2.w, fmaf(d3, v3.w, a.w))));
    }
    for (; e < end; e++) {
        int s0 = __ldg(&g_csr[e]);
        float d0 = g_dinv[s0];
        float4 v0 = h2[s0 * 16 + lane];
        a.x = fmaf(d0, v0.x, a.x);
        a.y = fmaf(d0, v0.y, a.y);
        a.z = fmaf(d0, v0.z, a.z);
        a.w = fmaf(d0, v0.w, a.w);
    }

    float4 o;
    o.x = fmaxf(fmaf(dv, a.x, bias[lane * 4 + 0]), 0.f);
    o.y = fmaxf(fmaf(dv, a.y, bias[lane * 4 + 1]), 0.f);
    o.z = fmaxf(fmaf(dv, a.z, bias[lane * 4 + 2]), 0.f);
    o.w = fmaxf(fmaf(dv, a.w, bias[lane * 4 + 3]), 0.f);
    ((float4*)g_x)[(long long)node * 16 + lane] = o;
}

// ---------------------------------------------------------------------------
extern "C" void kernel_launch(void* const* d_in, const int* in_sizes, int n_in,
                              void* d_out, int out_size) {
    const float* x    = (const float*)d_in[0];
    const void*  ei   = d_in[1];
    const float* Ws   = (const float*)d_in[2];
    const float* bs   = (const float*)d_in[3];
    const float* Wout = (const float*)d_in[4];
    const float* bout = (const float*)d_in[5];
    float* out = (float*)d_out;

    float *h2p, *xp;
    cudaGetSymbolAddress((void**)&h2p, g_h2);
    cudaGetSymbolAddress((void**)&xp,  g_x);

    cudaFuncSetAttribute(gemm_tc, cudaFuncAttributeMaxDynamicSharedMemorySize, SM_TOT);

    // Side stream + events, created once on the (uncaptured) correctness call.
    static cudaStream_t s2 = nullptr;
    static cudaEvent_t  ev_fork = nullptr, ev_g1 = nullptr;
    static cudaEvent_t  evA = nullptr, evB = nullptr, evM = nullptr;
    if (!s2) {
        cudaStreamCreateWithFlags(&s2, cudaStreamNonBlocking);
        cudaEventCreateWithFlags(&ev_fork, cudaEventDisableTiming);
        cudaEventCreateWithFlags(&ev_g1, cudaEventDisableTiming);
        cudaEventCreateWithFlags(&evA, cudaEventDisableTiming);
        cudaEventCreateWithFlags(&evB, cudaEventDisableTiming);
        cudaEventCreateWithFlags(&evM, cudaEventDisableTiming);
    }

    const int GB_E   = (NE + 255) / 256;
    const int GB_N   = (NN + 255) / 256;
    const int GB_MMF = (NN + 127) / 128;            // full-range gemm tiles
    const int T_A    = C0 / 128;                    // 391 tiles (chunk A)
    const int T_B    = (NN - C0 + 127) / 128;       // 391 tiles (chunk B)
    const int GA     = (C0 * 16 + 255) / 256;       // gather blocks chunk A
    const int GB     = ((NN - C0) * 16 + 255) / 256;

    // Fork: full GEMM-1 (independent of the CSR build) runs on s2.
    cudaEventRecord(ev_fork, 0);
    cudaStreamWaitEvent(s2, ev_fork, 0);
    gemm_tc<<<GB_MMF, 256, SM_TOT, s2>>>(x, Ws, nullptr, h2p, 0, NN);
    cudaEventRecord(ev_g1, s2);

    // CSR build on the main stream.
    degi_count<<<GB_E, 256>>>(ei);
    scan1<<<NSCB, SCAN_T>>>();
    scan23<<<GB_N, 256>>>();
    csr_fill<<<GB_E, 256>>>(ei);
    cudaStreamWaitEvent(0, ev_g1, 0);

    // Layer chain, chunk-pipelined: gather(A) -> gemm(A) on s2 while
    // gather(B) runs on stream 0; next layer waits for both gemms.
    for (int l = 0; l < 3; l++) {
        const float* bias = bs + l * D;
        const float* Wn   = (l < 2) ? (Ws + (l + 1) * D * D) : Wout;
        const float* bn   = (l < 2) ? nullptr : bout;
        float*       Yn   = (l < 2) ? h2p : out;

        gather_epi<<<GA, 256>>>(0, C0, bias);
        cudaEventRecord(evA, 0);
        gather_epi<<<GB, 256>>>(C0, NN, bias);
        cudaEventRecord(evB, 0);

        cudaStreamWaitEvent(s2, evA, 0);
        gemm_tc<<<T_A, 256, SM_TOT, s2>>>(xp, Wn, bn, Yn, 0, C0);
        cudaStreamWaitEvent(s2, evB, 0);
        gemm_tc<<<T_B, 256, SM_TOT, s2>>>(xp, Wn, bn, Yn, C0, NN);
        cudaEventRecord(evM, s2);
        cudaStreamWaitEvent(0, evM, 0);   // join (also rejoins capture at the end)
    }
}

// round 9
// speedup vs baseline: 1.0786x; 1.0786x over previous
#include <cuda_runtime.h>
#include <cuda_bf16.h>
#include <cstdint>

static constexpr int NN = 100000;   // nodes
static constexpr int D  = 64;       // feature dim
static constexpr int NE = 1000000;  // edges

static constexpr int SCAN_T = 512;
static constexpr int NSCB   = (NN + SCAN_T - 1) / SCAN_T;   // 196

// Scratch (device globals — no allocation allowed)
__device__ float          g_h2[NN * D];   // h = x @ W (unscaled, fp32)
__device__ unsigned short g_xh[NN * D];   // activations, bf16 hi plane
__device__ unsigned short g_xl[NN * D];   // activations, bf16 lo plane
__device__ float g_dinv[NN];
__device__ int   g_degi[NN];      // zero at entry (BSS first call; csr_fill re-zeros)
__device__ int   g_off [NN + 1];
__device__ int   g_cur [NN];
__device__ int   g_scan[NN];
__device__ int   g_bsum[NSCB];
__device__ int   g_csr [NE];      // src ids grouped by dst

// ---------------------------------------------------------------------------
// Per-block int64-vs-int32 detection (JAX may silently downcast edge_index).
__device__ __forceinline__ int block_detect64(const int* __restrict__ w) {
    __shared__ int s_flag;
    if (threadIdx.x == 0) s_flag = 0;
    __syncthreads();
    if (threadIdx.x < 64 && w[2 * threadIdx.x + 1]) atomicOr(&s_flag, 1);
    __syncthreads();
    return s_flag == 0;
}

__device__ __forceinline__ int edge_at(const void* ei, int is64, long long pos) {
    if (is64) return (int)((const long long*)ei)[pos];
    return ((const int*)ei)[pos];
}

__global__ void degi_count(const void* __restrict__ ei) {
    int is64 = block_detect64((const int*)ei);
    int e = blockIdx.x * 256 + threadIdx.x;
    if (e < NE) atomicAdd(&g_degi[edge_at(ei, is64, (long long)NE + e)], 1);
}

// ---- prefix scan ----------------------------------------------------------
__global__ void scan1() {
    __shared__ int s[SCAN_T];
    int i = blockIdx.x * SCAN_T + threadIdx.x;
    int v = (i < NN) ? g_degi[i] : 0;
    s[threadIdx.x] = v;
    __syncthreads();
    #pragma unroll
    for (int off = 1; off < SCAN_T; off <<= 1) {
        int t = (threadIdx.x >= off) ? s[threadIdx.x - off] : 0;
        __syncthreads();
        s[threadIdx.x] += t;
        __syncthreads();
    }
    if (i < NN) g_scan[i] = s[threadIdx.x];
    if (threadIdx.x == SCAN_T - 1) g_bsum[blockIdx.x] = s[threadIdx.x];
}

// Fused: per-block re-scan of block sums + offsets + cursor + dinv.
__global__ void scan23() {
    __shared__ int bs[256];
    int v = (threadIdx.x < NSCB) ? g_bsum[threadIdx.x] : 0;
    bs[threadIdx.x] = v;
    __syncthreads();
    #pragma unroll
    for (int off = 1; off < 256; off <<= 1) {
        int t = (threadIdx.x >= off) ? bs[threadIdx.x - off] : 0;
        __syncthreads();
        bs[threadIdx.x] += t;
        __syncthreads();
    }
    int i = blockIdx.x * 256 + threadIdx.x;
    if (i >= NN) return;
    int b  = i / SCAN_T;
    int di = g_degi[i];
    int incl = g_scan[i] + (b > 0 ? bs[b - 1] : 0);
    g_off[i + 1] = incl;
    if (i == 0) g_off[0] = 0;
    g_cur[i] = incl - di;
    g_dinv[i] = rsqrtf(1.0f + (float)di);
}

// Fill CSR; also re-zero g_degi so the NEXT invocation starts clean.
__global__ void csr_fill(const void* __restrict__ ei) {
    int is64 = block_detect64((const int*)ei);
    int e = blockIdx.x * 256 + threadIdx.x;
    if (e < NN) g_degi[e] = 0;
    if (e >= NE) return;
    int src = edge_at(ei, is64, e);
    int dst = edge_at(ei, is64, (long long)NE + e);
    int pos = atomicAdd(&g_cur[dst], 1);
    g_csr[pos] = src;
}

// ---------------------------------------------------------------------------
// Shared tensor-core GEMM machinery (mma.sync bf16, 3-pass compensation).
static constexpr int HSTR  = 72;   // halves per row (64 + 8 pad)
static constexpr int SM_AH = 0;
static constexpr int SM_AL = SM_AH + 128 * HSTR * 2;   // 18432
static constexpr int SM_BH = SM_AL + 128 * HSTR * 2;   // 36864
static constexpr int SM_BL = SM_BH + 64 * HSTR * 2;    // 46080
static constexpr int SM_TOT = SM_BL + 64 * HSTR * 2;   // 55296

__device__ __forceinline__ uint32_t smem_u32(const void* p) {
    uint32_t a;
    asm("{ .reg .u64 t; cvta.to.shared.u64 t, %1; cvt.u32.u64 %0, t; }"
        : "=r"(a) : "l"(p));
    return a;
}
__device__ __forceinline__ void ldsm4(uint32_t& r0, uint32_t& r1, uint32_t& r2,
                                      uint32_t& r3, uint32_t addr) {
    asm volatile("ldmatrix.sync.aligned.m8n8.x4.shared.b16 {%0,%1,%2,%3}, [%4];"
                 : "=r"(r0), "=r"(r1), "=r"(r2), "=r"(r3) : "r"(addr));
}
__device__ __forceinline__ void mma16816(float* c, const uint32_t* a,
                                         uint32_t b0, uint32_t b1) {
    asm volatile(
        "mma.sync.aligned.m16n8k16.row.col.f32.bf16.bf16.f32 "
        "{%0,%1,%2,%3}, {%4,%5,%6,%7}, {%8,%9}, {%0,%1,%2,%3};"
        : "+f"(c[0]), "+f"(c[1]), "+f"(c[2]), "+f"(c[3])
        : "r"(a[0]), "r"(a[1]), "r"(a[2]), "r"(a[3]), "r"(b0), "r"(b1));
}
__device__ __forceinline__ void split_bf16(float x, unsigned short& h, unsigned short& l) {
    __nv_bfloat16 hb = __float2bfloat16(x);
    __nv_bfloat16 lb = __float2bfloat16(x - __bfloat162float(hb));
    h = __bfloat16_as_ushort(hb);
    l = __bfloat16_as_ushort(lb);
}

// Fill B planes (W^T hi/lo) into smem; uses tid over 256 threads.
__device__ __forceinline__ void fill_B(char* smem, const float* __restrict__ W, int tid) {
    #pragma unroll
    for (int i = 0; i < 16; i++) {
        int idx = tid + i * 256;           // coalesced read of W
        int k = idx >> 6, n = idx & 63;
        unsigned short h, l;
        split_bf16(W[idx], h, l);
        uint32_t off = (uint32_t)(n * HSTR + k) * 2;
        *(unsigned short*)(smem + SM_BH + off) = h;
        *(unsigned short*)(smem + SM_BL + off) = l;
    }
}

// Mainloop + epilogue; assumes smem A/B planes ready, __syncthreads done.
__device__ __forceinline__ void mma_main_epi(
        char* smem, const float* __restrict__ bias, float* __restrict__ Y,
        long long base, int tid) {
    const int wid  = tid >> 5;
    const int lane = tid & 31;
    const uint32_t sb = smem_u32(smem);
    const int r0w = wid * 16;

    const int li  = lane >> 3;
    const int lw  = lane & 7;
    const uint32_t a_off =
        (uint32_t)(((r0w + (li & 1) * 8 + lw) * HSTR + (li >> 1) * 8) * 2);
    const uint32_t b_off =
        (uint32_t)((((li >> 1) * 8 + lw) * HSTR + (li & 1) * 8) * 2);

    float acc[8][4];
    #pragma unroll
    for (int nt = 0; nt < 8; nt++)
        #pragma unroll
        for (int q = 0; q < 4; q++) acc[nt][q] = 0.f;

    const uint32_t aBase[3] = { sb + SM_AH, sb + SM_AH, sb + SM_AL };
    const uint32_t bBase[3] = { sb + SM_BH, sb + SM_BL, sb + SM_BH };

    #pragma unroll
    for (int pass = 0; pass < 3; pass++) {
        #pragma unroll
        for (int kt = 0; kt < 4; kt++) {
            uint32_t a[4];
            ldsm4(a[0], a[1], a[2], a[3], aBase[pass] + a_off + kt * 32);
            #pragma unroll
            for (int ntp = 0; ntp < 4; ntp++) {
                uint32_t b0, b1, b2, b3;
                ldsm4(b0, b1, b2, b3,
                      bBase[pass] + b_off + (uint32_t)(ntp * 16 * HSTR * 2) + kt * 32);
                mma16816(acc[2 * ntp],     a, b0, b1);
                mma16816(acc[2 * ntp + 1], a, b2, b3);
            }
        }
    }

    const int rA = r0w + (lane >> 2);
    const int rB = rA + 8;
    long long gA = base + rA, gB = base + rB;
    bool vA = gA < NN, vB = gB < NN;
    #pragma unroll
    for (int nt = 0; nt < 8; nt++) {
        int cg = nt * 8 + (lane & 3) * 2;
        float bx = 0.f, by = 0.f;
        if (bias) { bx = bias[cg]; by = bias[cg + 1]; }
        if (vA) {
            float2 o = make_float2(acc[nt][0] + bx, acc[nt][1] + by);
            *(float2*)&Y[gA * 64 + cg] = o;
        }
        if (vB) {
            float2 o = make_float2(acc[nt][2] + bx, acc[nt][3] + by);
            *(float2*)&Y[gB * 64 + cg] = o;
        }
    }
}

// GEMM variant 1: fp32 input (layer 1 reads harness x). Converts in-kernel.
__global__ void __launch_bounds__(256) gemm_f32(
        const float* __restrict__ X, const float* __restrict__ W,
        const float* __restrict__ bias, float* __restrict__ Y) {
    extern __shared__ char smem[];
    const int tid  = threadIdx.x;
    const long long base = (long long)blockIdx.x * 128;

    #pragma unroll
    for (int i = 0; i < 8; i++) {
        int idx  = tid + i * 256;
        int row  = idx >> 4;
        int k    = (idx & 15) * 4;
        float4 v = make_float4(0.f, 0.f, 0.f, 0.f);
        if (base + row < NN)
            v = ((const float4*)X)[(base + row) * 16 + (k >> 2)];
        unsigned short h0, l0, h1, l1, h2v, l2v, h3, l3;
        split_bf16(v.x, h0, l0); split_bf16(v.y, h1, l1);
        split_bf16(v.z, h2v, l2v); split_bf16(v.w, h3, l3);
        unsigned long long hp = (unsigned long long)h0
            | ((unsigned long long)h1 << 16) | ((unsigned long long)h2v << 32)
            | ((unsigned long long)h3 << 48);
        unsigned long long lp = (unsigned long long)l0
            | ((unsigned long long)l1 << 16) | ((unsigned long long)l2v << 32)
            | ((unsigned long long)l3 << 48);
        uint32_t off = (uint32_t)(row * HSTR + k) * 2;
        *(unsigned long long*)(smem + SM_AH + off) = hp;
        *(unsigned long long*)(smem + SM_AL + off) = lp;
    }
    fill_B(smem, W, tid);
    __syncthreads();
    mma_main_epi(smem, bias, Y, base, tid);
}

// GEMM variant 2: pre-split bf16 planes input (layers 2..4). Pure copy fill.
__global__ void __launch_bounds__(256) gemm_bf(
        const float* __restrict__ W, const float* __restrict__ bias,
        float* __restrict__ Y) {
    extern __shared__ char smem[];
    const int tid  = threadIdx.x;
    const long long base = (long long)blockIdx.x * 128;

    // A-fill: 128 rows x 64 halves per plane = 1024 uint4 per plane.
    #pragma unroll
    for (int i = 0; i < 4; i++) {
        int idx = tid + i * 256;           // uint4 index
        int row = idx >> 3;
        int k8  = (idx & 7) * 8;
        uint4 h = make_uint4(0, 0, 0, 0), l = make_uint4(0, 0, 0, 0);
        if (base + row < NN) {
            long long g = (base + row) * 8 + (idx & 7);
            h = ((const uint4*)g_xh)[g];
            l = ((const uint4*)g_xl)[g];
        }
        uint32_t off = (uint32_t)(row * HSTR + k8) * 2;   // 144*row + 16*k8/8: 16B aligned
        *(uint4*)(smem + SM_AH + off) = h;
        *(uint4*)(smem + SM_AL + off) = l;
    }
    fill_B(smem, W, tid);
    __syncthreads();
    mma_main_epi(smem, bias, Y, base, tid);
}

// ---------------------------------------------------------------------------
// CSR gather + fused epilogue (h unscaled):
//   x'[v] = relu( dinv[v] * ( dinv[v]*h[v] + sum_src dinv[s]*h[s] ) + b )
// Output written as bf16 hi/lo planes (exact Ah/Al for the next GEMM).
__global__ void __launch_bounds__(256) gather_epi(const float* __restrict__ bias) {
    int t    = blockIdx.x * 256 + threadIdx.x;
    int node = t >> 4;
    if (node >= NN) return;
    int lane = t & 15;

    const float4* __restrict__ h2 = (const float4*)g_h2;
    int beg = g_off[node];
    int end = g_off[node + 1];
    float dv = g_dinv[node];

    float4 hs = h2[node * 16 + lane];
    float4 a;
    a.x = dv * hs.x; a.y = dv * hs.y; a.z = dv * hs.z; a.w = dv * hs.w;

    int e = beg;
    for (; e + 3 < end; e += 4) {
        int s0 = __ldg(&g_csr[e]);
        int s1 = __ldg(&g_csr[e + 1]);
        int s2 = __ldg(&g_csr[e + 2]);
        int s3 = __ldg(&g_csr[e + 3]);
        float d0 = g_dinv[s0], d1 = g_dinv[s1], d2 = g_dinv[s2], d3 = g_dinv[s3];
        float4 v0 = h2[s0 * 16 + lane];
        float4 v1 = h2[s1 * 16 + lane];
        float4 v2 = h2[s2 * 16 + lane];
        float4 v3 = h2[s3 * 16 + lane];
        a.x = fmaf(d0, v0.x, fmaf(d1, v1.x, fmaf(d2, v2.x, fmaf(d3, v3.x, a.x))));
        a.y = fmaf(d0, v0.y, fmaf(d1, v1.y, fmaf(d2, v2.y, fmaf(d3, v3.y, a.y))));
        a.z = fmaf(d0, v0.z, fmaf(d1, v1.z, fmaf(d2, v2.z, fmaf(d3, v3.z, a.z))));
        a.w = fmaf(d0, v0.w, fmaf(d1, v1.w, fmaf(d2, v2.w, fmaf(d3, v3.w, a.w))));
    }
    for (; e < end; e++) {
        int s0 = __ldg(&g_csr[e]);
        float d0 = g_dinv[s0];
        float4 v0 = h2[s0 * 16 + lane];
        a.x = fmaf(d0, v0.x, a.x);
        a.y = fmaf(d0, v0.y, a.y);
        a.z = fmaf(d0, v0.z, a.z);
        a.w = fmaf(d0, v0.w, a.w);
    }

    float4 o;
    o.x = fmaxf(fmaf(dv, a.x, bias[lane * 4 + 0]), 0.f);
    o.y = fmaxf(fmaf(dv, a.y, bias[lane * 4 + 1]), 0.f);
    o.z = fmaxf(fmaf(dv, a.z, bias[lane * 4 + 2]), 0.f);
    o.w = fmaxf(fmaf(dv, a.w, bias[lane * 4 + 3]), 0.f);

    unsigned short h0, l0, h1, l1, h2s, l2s, h3, l3;
    split_bf16(o.x, h0, l0); split_bf16(o.y, h1, l1);
    split_bf16(o.z, h2s, l2s); split_bf16(o.w, h3, l3);
    ushort4 hp = make_ushort4(h0, h1, h2s, h3);
    ushort4 lp = make_ushort4(l0, l1, l2s, l3);
    ((ushort4*)g_xh)[node * 16 + lane] = hp;
    ((ushort4*)g_xl)[node * 16 + lane] = lp;
}

// ---------------------------------------------------------------------------
extern "C" void kernel_launch(void* const* d_in, const int* in_sizes, int n_in,
                              void* d_out, int out_size) {
    const float* x    = (const float*)d_in[0];
    const void*  ei   = d_in[1];
    const float* Ws   = (const float*)d_in[2];
    const float* bs   = (const float*)d_in[3];
    const float* Wout = (const float*)d_in[4];
    const float* bout = (const float*)d_in[5];
    float* out = (float*)d_out;

    float* h2p;
    cudaGetSymbolAddress((void**)&h2p, g_h2);

    cudaFuncSetAttribute(gemm_f32, cudaFuncAttributeMaxDynamicSharedMemorySize, SM_TOT);
    cudaFuncSetAttribute(gemm_bf,  cudaFuncAttributeMaxDynamicSharedMemorySize, SM_TOT);

    // Side stream + events, created once on the (uncaptured) correctness call.
    static cudaStream_t s2 = nullptr;
    static cudaEvent_t  ev_fork = nullptr, ev_g1 = nullptr;
    if (!s2) {
        cudaStreamCreateWithFlags(&s2, cudaStreamNonBlocking);
        cudaEventCreateWithFlags(&ev_fork, cudaEventDisableTiming);
        cudaEventCreateWithFlags(&ev_g1, cudaEventDisableTiming);
    }

    const int GB_E  = (NE + 255) / 256;
    const int GB_N  = (NN + 255) / 256;
    const int GB_MM = (NN + 127) / 128;
    const int GB_G  = (NN * 16 + 255) / 256;

    // Fork: GEMM-1 (independent of the CSR build) runs on s2.
    cudaEventRecord(ev_fork, 0);
    cudaStreamWaitEvent(s2, ev_fork, 0);
    gemm_f32<<<GB_MM, 256, SM_TOT, s2>>>(x, Ws, nullptr, h2p);
    cudaEventRecord(ev_g1, s2);

    // CSR build on the main stream.
    degi_count<<<GB_E, 256>>>(ei);
    scan1<<<NSCB, SCAN_T>>>();
    scan23<<<GB_N, 256>>>();
    csr_fill<<<GB_E, 256>>>(ei);

    // Join, then the serial layer chain (bf16-plane handoff gather -> gemm).
    cudaStreamWaitEvent(0, ev_g1, 0);
    gather_epi<<<GB_G, 256>>>(bs);
    gemm_bf<<<GB_MM, 256, SM_TOT>>>(Ws + 1 * D * D, nullptr, h2p);
    gather_epi<<<GB_G, 256>>>(bs + 1 * D);
    gemm_bf<<<GB_MM, 256, SM_TOT>>>(Ws + 2 * D * D, nullptr, h2p);
    gather_epi<<<GB_G, 256>>>(bs + 2 * D);
    gemm_bf<<<GB_MM, 256, SM_TOT>>>(Wout, bout, out);
}

// round 10
// speedup vs baseline: 1.1180x; 1.0365x over previous
#include <cuda_runtime.h>
#include <cuda_bf16.h>
#include <cuda_fp16.h>
#include <cstdint>

static constexpr int NN = 100000;   // nodes
static constexpr int D  = 64;       // feature dim
static constexpr int NE = 1000000;  // edges

static constexpr int SCAN_T = 512;
static constexpr int NSCB   = (NN + SCAN_T - 1) / SCAN_T;   // 196

// Scratch (device globals — no allocation allowed)
__device__ uint4          g_h2h[NN * 8];  // h = x @ W, fp16 (64 halves = 8 uint4/row)
__device__ unsigned short g_xh[NN * D];   // activations, bf16 hi plane
__device__ unsigned short g_xl[NN * D];   // activations, bf16 lo plane
__device__ float g_dinv[NN];
__device__ int   g_degi[NN];      // zero at entry (BSS first call; csr_fill re-zeros)
__device__ int   g_off [NN + 1];
__device__ int   g_cur [NN];
__device__ int   g_scan[NN];
__device__ int   g_bsum[NSCB];
__device__ int   g_csr [NE];      // src ids grouped by dst

// ---------------------------------------------------------------------------
// Per-block int64-vs-int32 detection (JAX may silently downcast edge_index).
__device__ __forceinline__ int block_detect64(const int* __restrict__ w) {
    __shared__ int s_flag;
    if (threadIdx.x == 0) s_flag = 0;
    __syncthreads();
    if (threadIdx.x < 64 && w[2 * threadIdx.x + 1]) atomicOr(&s_flag, 1);
    __syncthreads();
    return s_flag == 0;
}

__device__ __forceinline__ int edge_at(const void* ei, int is64, long long pos) {
    if (is64) return (int)((const long long*)ei)[pos];
    return ((const int*)ei)[pos];
}

__global__ void degi_count(const void* __restrict__ ei) {
    int is64 = block_detect64((const int*)ei);
    int e = blockIdx.x * 256 + threadIdx.x;
    if (e < NE) atomicAdd(&g_degi[edge_at(ei, is64, (long long)NE + e)], 1);
}

// ---- prefix scan ----------------------------------------------------------
__global__ void scan1() {
    __shared__ int s[SCAN_T];
    int i = blockIdx.x * SCAN_T + threadIdx.x;
    int v = (i < NN) ? g_degi[i] : 0;
    s[threadIdx.x] = v;
    __syncthreads();
    #pragma unroll
    for (int off = 1; off < SCAN_T; off <<= 1) {
        int t = (threadIdx.x >= off) ? s[threadIdx.x - off] : 0;
        __syncthreads();
        s[threadIdx.x] += t;
        __syncthreads();
    }
    if (i < NN) g_scan[i] = s[threadIdx.x];
    if (threadIdx.x == SCAN_T - 1) g_bsum[blockIdx.x] = s[threadIdx.x];
}

// Fused: per-block re-scan of block sums + offsets + cursor + dinv.
__global__ void scan23() {
    __shared__ int bs[256];
    int v = (threadIdx.x < NSCB) ? g_bsum[threadIdx.x] : 0;
    bs[threadIdx.x] = v;
    __syncthreads();
    #pragma unroll
    for (int off = 1; off < 256; off <<= 1) {
        int t = (threadIdx.x >= off) ? bs[threadIdx.x - off] : 0;
        __syncthreads();
        bs[threadIdx.x] += t;
        __syncthreads();
    }
    int i = blockIdx.x * 256 + threadIdx.x;
    if (i >= NN) return;
    int b  = i / SCAN_T;
    int di = g_degi[i];
    int incl = g_scan[i] + (b > 0 ? bs[b - 1] : 0);
    g_off[i + 1] = incl;
    if (i == 0) g_off[0] = 0;
    g_cur[i] = incl - di;
    g_dinv[i] = rsqrtf(1.0f + (float)di);
}

// Fill CSR; also re-zero g_degi so the NEXT invocation starts clean.
__global__ void csr_fill(const void* __restrict__ ei) {
    int is64 = block_detect64((const int*)ei);
    int e = blockIdx.x * 256 + threadIdx.x;
    if (e < NN) g_degi[e] = 0;
    if (e >= NE) return;
    int src = edge_at(ei, is64, e);
    int dst = edge_at(ei, is64, (long long)NE + e);
    int pos = atomicAdd(&g_cur[dst], 1);
    g_csr[pos] = src;
}

// ---------------------------------------------------------------------------
// Shared tensor-core GEMM machinery (mma.sync bf16, 3-pass compensation).
static constexpr int HSTR  = 72;   // halves per row (64 + 8 pad)
static constexpr int SM_AH = 0;
static constexpr int SM_AL = SM_AH + 128 * HSTR * 2;   // 18432
static constexpr int SM_BH = SM_AL + 128 * HSTR * 2;   // 36864
static constexpr int SM_BL = SM_BH + 64 * HSTR * 2;    // 46080
static constexpr int SM_TOT = SM_BL + 64 * HSTR * 2;   // 55296

__device__ __forceinline__ uint32_t smem_u32(const void* p) {
    uint32_t a;
    asm("{ .reg .u64 t; cvta.to.shared.u64 t, %1; cvt.u32.u64 %0, t; }"
        : "=r"(a) : "l"(p));
    return a;
}
__device__ __forceinline__ void ldsm4(uint32_t& r0, uint32_t& r1, uint32_t& r2,
                                      uint32_t& r3, uint32_t addr) {
    asm volatile("ldmatrix.sync.aligned.m8n8.x4.shared.b16 {%0,%1,%2,%3}, [%4];"
                 : "=r"(r0), "=r"(r1), "=r"(r2), "=r"(r3) : "r"(addr));
}
__device__ __forceinline__ void mma16816(float* c, const uint32_t* a,
                                         uint32_t b0, uint32_t b1) {
    asm volatile(
        "mma.sync.aligned.m16n8k16.row.col.f32.bf16.bf16.f32 "
        "{%0,%1,%2,%3}, {%4,%5,%6,%7}, {%8,%9}, {%0,%1,%2,%3};"
        : "+f"(c[0]), "+f"(c[1]), "+f"(c[2]), "+f"(c[3])
        : "r"(a[0]), "r"(a[1]), "r"(a[2]), "r"(a[3]), "r"(b0), "r"(b1));
}
__device__ __forceinline__ void split_bf16(float x, unsigned short& h, unsigned short& l) {
    __nv_bfloat16 hb = __float2bfloat16(x);
    __nv_bfloat16 lb = __float2bfloat16(x - __bfloat162float(hb));
    h = __bfloat16_as_ushort(hb);
    l = __bfloat16_as_ushort(lb);
}

// Fill B planes (W^T hi/lo) into smem; uses tid over 256 threads.
__device__ __forceinline__ void fill_B(char* smem, const float* __restrict__ W, int tid) {
    #pragma unroll
    for (int i = 0; i < 16; i++) {
        int idx = tid + i * 256;           // coalesced read of W
        int k = idx >> 6, n = idx & 63;
        unsigned short h, l;
        split_bf16(W[idx], h, l);
        uint32_t off = (uint32_t)(n * HSTR + k) * 2;
        *(unsigned short*)(smem + SM_BH + off) = h;
        *(unsigned short*)(smem + SM_BL + off) = l;
    }
}

// Mainloop + epilogue. If Yh != nullptr, store fp16 to Yh (no bias);
// else store fp32 (+bias) to Yf.
__device__ __forceinline__ void mma_main_epi(
        char* smem, const float* __restrict__ bias,
        float* __restrict__ Yf, __half* __restrict__ Yh,
        long long base, int tid) {
    const int wid  = tid >> 5;
    const int lane = tid & 31;
    const uint32_t sb = smem_u32(smem);
    const int r0w = wid * 16;

    const int li  = lane >> 3;
    const int lw  = lane & 7;
    const uint32_t a_off =
        (uint32_t)(((r0w + (li & 1) * 8 + lw) * HSTR + (li >> 1) * 8) * 2);
    const uint32_t b_off =
        (uint32_t)((((li >> 1) * 8 + lw) * HSTR + (li & 1) * 8) * 2);

    float acc[8][4];
    #pragma unroll
    for (int nt = 0; nt < 8; nt++)
        #pragma unroll
        for (int q = 0; q < 4; q++) acc[nt][q] = 0.f;

    const uint32_t aBase[3] = { sb + SM_AH, sb + SM_AH, sb + SM_AL };
    const uint32_t bBase[3] = { sb + SM_BH, sb + SM_BL, sb + SM_BH };

    #pragma unroll
    for (int pass = 0; pass < 3; pass++) {
        #pragma unroll
        for (int kt = 0; kt < 4; kt++) {
            uint32_t a[4];
            ldsm4(a[0], a[1], a[2], a[3], aBase[pass] + a_off + kt * 32);
            #pragma unroll
            for (int ntp = 0; ntp < 4; ntp++) {
                uint32_t b0, b1, b2, b3;
                ldsm4(b0, b1, b2, b3,
                      bBase[pass] + b_off + (uint32_t)(ntp * 16 * HSTR * 2) + kt * 32);
                mma16816(acc[2 * ntp],     a, b0, b1);
                mma16816(acc[2 * ntp + 1], a, b2, b3);
            }
        }
    }

    const int rA = r0w + (lane >> 2);
    const int rB = rA + 8;
    long long gA = base + rA, gB = base + rB;
    bool vA = gA < NN, vB = gB < NN;
    #pragma unroll
    for (int nt = 0; nt < 8; nt++) {
        int cg = nt * 8 + (lane & 3) * 2;
        if (Yh) {
            if (vA) *(__half2*)&Yh[gA * 64 + cg] =
                __floats2half2_rn(acc[nt][0], acc[nt][1]);
            if (vB) *(__half2*)&Yh[gB * 64 + cg] =
                __floats2half2_rn(acc[nt][2], acc[nt][3]);
        } else {
            float bx = 0.f, by = 0.f;
            if (bias) { bx = bias[cg]; by = bias[cg + 1]; }
            if (vA) {
                float2 o = make_float2(acc[nt][0] + bx, acc[nt][1] + by);
                *(float2*)&Yf[gA * 64 + cg] = o;
            }
            if (vB) {
                float2 o = make_float2(acc[nt][2] + bx, acc[nt][3] + by);
                *(float2*)&Yf[gB * 64 + cg] = o;
            }
        }
    }
}

// GEMM variant 1: fp32 input (layer 1 reads harness x). Converts in-kernel.
__global__ void __launch_bounds__(256) gemm_f32(
        const float* __restrict__ X, const float* __restrict__ W,
        __half* __restrict__ Yh) {
    extern __shared__ char smem[];
    const int tid  = threadIdx.x;
    const long long base = (long long)blockIdx.x * 128;

    #pragma unroll
    for (int i = 0; i < 8; i++) {
        int idx  = tid + i * 256;
        int row  = idx >> 4;
        int k    = (idx & 15) * 4;
        float4 v = make_float4(0.f, 0.f, 0.f, 0.f);
        if (base + row < NN)
            v = ((const float4*)X)[(base + row) * 16 + (k >> 2)];
        unsigned short h0, l0, h1, l1, h2v, l2v, h3, l3;
        split_bf16(v.x, h0, l0); split_bf16(v.y, h1, l1);
        split_bf16(v.z, h2v, l2v); split_bf16(v.w, h3, l3);
        unsigned long long hp = (unsigned long long)h0
            | ((unsigned long long)h1 << 16) | ((unsigned long long)h2v << 32)
            | ((unsigned long long)h3 << 48);
        unsigned long long lp = (unsigned long long)l0
            | ((unsigned long long)l1 << 16) | ((unsigned long long)l2v << 32)
            | ((unsigned long long)l3 << 48);
        uint32_t off = (uint32_t)(row * HSTR + k) * 2;
        *(unsigned long long*)(smem + SM_AH + off) = hp;
        *(unsigned long long*)(smem + SM_AL + off) = lp;
    }
    fill_B(smem, W, tid);
    __syncthreads();
    mma_main_epi(smem, nullptr, nullptr, Yh, base, tid);
}

// GEMM variant 2: pre-split bf16 planes input (layers 2..4). Pure copy fill.
__global__ void __launch_bounds__(256) gemm_bf(
        const float* __restrict__ W, const float* __restrict__ bias,
        float* __restrict__ Yf, __half* __restrict__ Yh) {
    extern __shared__ char smem[];
    const int tid  = threadIdx.x;
    const long long base = (long long)blockIdx.x * 128;

    // A-fill: 128 rows x 64 halves per plane = 1024 uint4 per plane.
    #pragma unroll
    for (int i = 0; i < 4; i++) {
        int idx = tid + i * 256;           // uint4 index
        int row = idx >> 3;
        int k8  = (idx & 7) * 8;
        uint4 h = make_uint4(0, 0, 0, 0), l = make_uint4(0, 0, 0, 0);
        if (base + row < NN) {
            long long g = (base + row) * 8 + (idx & 7);
            h = ((const uint4*)g_xh)[g];
            l = ((const uint4*)g_xl)[g];
        }
        uint32_t off = (uint32_t)(row * HSTR + k8) * 2;
        *(uint4*)(smem + SM_AH + off) = h;
        *(uint4*)(smem + SM_AL + off) = l;
    }
    fill_B(smem, W, tid);
    __syncthreads();
    mma_main_epi(smem, bias, Yf, Yh, base, tid);
}

// ---------------------------------------------------------------------------
// CSR gather + fused epilogue, h stored fp16 (accumulate fp32):
//   x'[v] = relu( dinv[v] * ( dinv[v]*h[v] + sum_src dinv[s]*h[s] ) + b )
// 8 threads per node; each lane handles 8 consecutive cols (one uint4 = 16B).
// Output written as bf16 hi/lo planes (exact Ah/Al for the next GEMM).
__global__ void __launch_bounds__(256) gather_epi(const float* __restrict__ bias) {
    int t    = blockIdx.x * 256 + threadIdx.x;
    int node = t >> 3;
    if (node >= NN) return;
    int lane = t & 7;

    int beg = g_off[node];
    int end = g_off[node + 1];
    float dv = g_dinv[node];

    float a[8];
    {
        uint4 hv = g_h2h[node * 8 + lane];
        const __half2* p = (const __half2*)&hv;
        #pragma unroll
        for (int q = 0; q < 4; q++) {
            float2 f = __half22float2(p[q]);
            a[2 * q]     = dv * f.x;
            a[2 * q + 1] = dv * f.y;
        }
    }

    int e = beg;
    for (; e + 1 < end; e += 2) {
        int s0 = __ldg(&g_csr[e]);
        int s1 = __ldg(&g_csr[e + 1]);
        float d0 = g_dinv[s0], d1 = g_dinv[s1];
        uint4 v0 = g_h2h[s0 * 8 + lane];
        uint4 v1 = g_h2h[s1 * 8 + lane];
        const __half2* p0 = (const __half2*)&v0;
        const __half2* p1 = (const __half2*)&v1;
        #pragma unroll
        for (int q = 0; q < 4; q++) {
            float2 f0 = __half22float2(p0[q]);
            float2 f1 = __half22float2(p1[q]);
            a[2 * q]     = fmaf(d0, f0.x, fmaf(d1, f1.x, a[2 * q]));
            a[2 * q + 1] = fmaf(d0, f0.y, fmaf(d1, f1.y, a[2 * q + 1]));
        }
    }
    if (e < end) {
        int s0 = __ldg(&g_csr[e]);
        float d0 = g_dinv[s0];
        uint4 v0 = g_h2h[s0 * 8 + lane];
        const __half2* p0 = (const __half2*)&v0;
        #pragma unroll
        for (int q = 0; q < 4; q++) {
            float2 f0 = __half22float2(p0[q]);
            a[2 * q]     = fmaf(d0, f0.x, a[2 * q]);
            a[2 * q + 1] = fmaf(d0, f0.y, a[2 * q + 1]);
        }
    }

    unsigned short hs[8], ls[8];
    #pragma unroll
    for (int q = 0; q < 8; q++) {
        float o = fmaxf(fmaf(dv, a[q], bias[lane * 8 + q]), 0.f);
        split_bf16(o, hs[q], ls[q]);
    }
    ushort4* xh4 = (ushort4*)g_xh;
    ushort4* xl4 = (ushort4*)g_xl;
    xh4[node * 16 + lane * 2]     = make_ushort4(hs[0], hs[1], hs[2], hs[3]);
    xh4[node * 16 + lane * 2 + 1] = make_ushort4(hs[4], hs[5], hs[6], hs[7]);
    xl4[node * 16 + lane * 2]     = make_ushort4(ls[0], ls[1], ls[2], ls[3]);
    xl4[node * 16 + lane * 2 + 1] = make_ushort4(ls[4], ls[5], ls[6], ls[7]);
}

// ---------------------------------------------------------------------------
extern "C" void kernel_launch(void* const* d_in, const int* in_sizes, int n_in,
                              void* d_out, int out_size) {
    const float* x    = (const float*)d_in[0];
    const void*  ei   = d_in[1];
    const float* Ws   = (const float*)d_in[2];
    const float* bs   = (const float*)d_in[3];
    const float* Wout = (const float*)d_in[4];
    const float* bout = (const float*)d_in[5];
    float* out = (float*)d_out;

    __half* h2p;
    cudaGetSymbolAddress((void**)&h2p, g_h2h);

    cudaFuncSetAttribute(gemm_f32, cudaFuncAttributeMaxDynamicSharedMemorySize, SM_TOT);
    cudaFuncSetAttribute(gemm_bf,  cudaFuncAttributeMaxDynamicSharedMemorySize, SM_TOT);

    // Side stream + events, created once on the (uncaptured) correctness call.
    static cudaStream_t s2 = nullptr;
    static cudaEvent_t  ev_fork = nullptr, ev_g1 = nullptr;
    if (!s2) {
        cudaStreamCreateWithFlags(&s2, cudaStreamNonBlocking);
        cudaEventCreateWithFlags(&ev_fork, cudaEventDisableTiming);
        cudaEventCreateWithFlags(&ev_g1, cudaEventDisableTiming);
    }

    const int GB_E  = (NE + 255) / 256;
    const int GB_N  = (NN + 255) / 256;
    const int GB_MM = (NN + 127) / 128;
    const int GB_G  = (NN * 8 + 255) / 256;

    // Fork: GEMM-1 (independent of the CSR build) runs on s2.
    cudaEventRecord(ev_fork, 0);
    cudaStreamWaitEvent(s2, ev_fork, 0);
    gemm_f32<<<GB_MM, 256, SM_TOT, s2>>>(x, Ws, h2p);
    cudaEventRecord(ev_g1, s2);

    // CSR build on the main stream.
    degi_count<<<GB_E, 256>>>(ei);
    scan1<<<NSCB, SCAN_T>>>();
    scan23<<<GB_N, 256>>>();
    csr_fill<<<GB_E, 256>>>(ei);

    // Join, then the serial layer chain (bf16-plane handoff gather -> gemm,
    // fp16 h hand-off gemm -> gather).
    cudaStreamWaitEvent(0, ev_g1, 0);
    gather_epi<<<GB_G, 256>>>(bs);
    gemm_bf<<<GB_MM, 256, SM_TOT>>>(Ws + 1 * D * D, nullptr, nullptr, h2p);
    gather_epi<<<GB_G, 256>>>(bs + 1 * D);
    gemm_bf<<<GB_MM, 256, SM_TOT>>>(Ws + 2 * D * D, nullptr, nullptr, h2p);
    gather_epi<<<GB_G, 256>>>(bs + 2 * D);
    gemm_bf<<<GB_MM, 256, SM_TOT>>>(Wout, bout, out, nullptr);
}

// round 11
// speedup vs baseline: 1.2783x; 1.1435x over previous
#include <cuda_runtime.h>
#include <cuda_bf16.h>
#include <cuda_fp16.h>
#include <cstdint>

static constexpr int NN = 100000;   // nodes
static constexpr int D  = 64;       // feature dim
static constexpr int NE = 1000000;  // edges

static constexpr int SCAN_T = 512;
static constexpr int NSCB   = (NN + SCAN_T - 1) / SCAN_T;   // 196

// Scratch (device globals — no allocation allowed)
__device__ uint4          g_hA[NN * 8];   // h fp16 ping (64 halves = 8 uint4/row)
__device__ uint4          g_hB[NN * 8];   // h fp16 pong
__device__ unsigned short g_wh[3 * 4096]; // W planes hi, [n*64+k], layers {1,2,out}
__device__ unsigned short g_wl[3 * 4096]; // W planes lo
__device__ float g_dinv[NN];
__device__ int   g_degi[NN];      // zero at entry (BSS first call; csr_fill re-zeros)
__device__ int   g_off [NN + 1];
__device__ int   g_cur [NN];
__device__ int   g_scan[NN];
__device__ int   g_bsum[NSCB];
__device__ int   g_csr [NE];      // src ids grouped by dst

// ---------------------------------------------------------------------------
// Per-block int64-vs-int32 detection (JAX may silently downcast edge_index).
__device__ __forceinline__ int block_detect64(const int* __restrict__ w) {
    __shared__ int s_flag;
    if (threadIdx.x == 0) s_flag = 0;
    __syncthreads();
    if (threadIdx.x < 64 && w[2 * threadIdx.x + 1]) atomicOr(&s_flag, 1);
    __syncthreads();
    return s_flag == 0;
}

__device__ __forceinline__ int edge_at(const void* ei, int is64, long long pos) {
    if (is64) return (int)((const long long*)ei)[pos];
    return ((const int*)ei)[pos];
}

__global__ void degi_count(const void* __restrict__ ei) {
    int is64 = block_detect64((const int*)ei);
    int e = blockIdx.x * 256 + threadIdx.x;
    if (e < NE) atomicAdd(&g_degi[edge_at(ei, is64, (long long)NE + e)], 1);
}

// ---- prefix scan ----------------------------------------------------------
__global__ void scan1() {
    __shared__ int s[SCAN_T];
    int i = blockIdx.x * SCAN_T + threadIdx.x;
    int v = (i < NN) ? g_degi[i] : 0;
    s[threadIdx.x] = v;
    __syncthreads();
    #pragma unroll
    for (int off = 1; off < SCAN_T; off <<= 1) {
        int t = (threadIdx.x >= off) ? s[threadIdx.x - off] : 0;
        __syncthreads();
        s[threadIdx.x] += t;
        __syncthreads();
    }
    if (i < NN) g_scan[i] = s[threadIdx.x];
    if (threadIdx.x == SCAN_T - 1) g_bsum[blockIdx.x] = s[threadIdx.x];
}

// Fused: per-block re-scan of block sums + offsets + cursor + dinv.
__global__ void scan23() {
    __shared__ int bs[256];
    int v = (threadIdx.x < NSCB) ? g_bsum[threadIdx.x] : 0;
    bs[threadIdx.x] = v;
    __syncthreads();
    #pragma unroll
    for (int off = 1; off < 256; off <<= 1) {
        int t = (threadIdx.x >= off) ? bs[threadIdx.x - off] : 0;
        __syncthreads();
        bs[threadIdx.x] += t;
        __syncthreads();
    }
    int i = blockIdx.x * 256 + threadIdx.x;
    if (i >= NN) return;
    int b  = i / SCAN_T;
    int di = g_degi[i];
    int incl = g_scan[i] + (b > 0 ? bs[b - 1] : 0);
    g_off[i + 1] = incl;
    if (i == 0) g_off[0] = 0;
    g_cur[i] = incl - di;
    g_dinv[i] = rsqrtf(1.0f + (float)di);
}

// Fill CSR; also re-zero g_degi so the NEXT invocation starts clean.
__global__ void csr_fill(const void* __restrict__ ei) {
    int is64 = block_detect64((const int*)ei);
    int e = blockIdx.x * 256 + threadIdx.x;
    if (e < NN) g_degi[e] = 0;
    if (e >= NE) return;
    int src = edge_at(ei, is64, e);
    int dst = edge_at(ei, is64, (long long)NE + e);
    int pos = atomicAdd(&g_cur[dst], 1);
    g_csr[pos] = src;
}

// ---------------------------------------------------------------------------
__device__ __forceinline__ void split_bf16(float x, unsigned short& h, unsigned short& l) {
    __nv_bfloat16 hb = __float2bfloat16(x);
    __nv_bfloat16 lb = __float2bfloat16(x - __bfloat162float(hb));
    h = __bfloat16_as_ushort(hb);
    l = __bfloat16_as_ushort(lb);
}

// Pre-split W planes for layers {1,2,out}: [n*64+k] hi/lo from row-major W[k][n].
__global__ void wconv(const float* __restrict__ Ws, const float* __restrict__ Wout) {
    int idx = blockIdx.x * 256 + threadIdx.x;     // 0 .. 3*4096
    if (idx >= 3 * 4096) return;
    int l   = idx >> 12;
    int rem = idx & 4095;
    int k = rem >> 6, n = rem & 63;
    float v = (l < 2) ? Ws[(l + 1) * 4096 + rem] : Wout[rem];
    unsigned short h, lo;
    split_bf16(v, h, lo);
    g_wh[l * 4096 + n * 64 + k] = h;
    g_wl[l * 4096 + n * 64 + k] = lo;
}

// ---------------------------------------------------------------------------
// Tensor-core machinery (mma.sync bf16, 3-pass compensation).
static constexpr int HSTR  = 72;   // halves per row (64 + 8 pad)

__device__ __forceinline__ uint32_t smem_u32(const void* p) {
    uint32_t a;
    asm("{ .reg .u64 t; cvta.to.shared.u64 t, %1; cvt.u32.u64 %0, t; }"
        : "=r"(a) : "l"(p));
    return a;
}
__device__ __forceinline__ void ldsm4(uint32_t& r0, uint32_t& r1, uint32_t& r2,
                                      uint32_t& r3, uint32_t addr) {
    asm volatile("ldmatrix.sync.aligned.m8n8.x4.shared.b16 {%0,%1,%2,%3}, [%4];"
                 : "=r"(r0), "=r"(r1), "=r"(r2), "=r"(r3) : "r"(addr));
}
__device__ __forceinline__ void mma16816(float* c, const uint32_t* a,
                                         uint32_t b0, uint32_t b1) {
    asm volatile(
        "mma.sync.aligned.m16n8k16.row.col.f32.bf16.bf16.f32 "
        "{%0,%1,%2,%3}, {%4,%5,%6,%7}, {%8,%9}, {%0,%1,%2,%3};"
        : "+f"(c[0]), "+f"(c[1]), "+f"(c[2]), "+f"(c[3])
        : "r"(a[0]), "r"(a[1]), "r"(a[2]), "r"(a[3]), "r"(b0), "r"(b1));
}

// ======================= Layer-1 GEMM (128-row tile) =======================
static constexpr int G_AH = 0;
static constexpr int G_AL = G_AH + 128 * HSTR * 2;   // 18432
static constexpr int G_BH = G_AL + 128 * HSTR * 2;   // 36864
static constexpr int G_BL = G_BH + 64 * HSTR * 2;    // 46080
static constexpr int G_TOT = G_BL + 64 * HSTR * 2;   // 55296

__global__ void __launch_bounds__(256) gemm_f32(
        const float* __restrict__ X, const float* __restrict__ W,
        __half* __restrict__ Yh) {
    extern __shared__ char smem[];
    const int tid  = threadIdx.x;
    const long long base = (long long)blockIdx.x * 128;

    #pragma unroll
    for (int i = 0; i < 8; i++) {
        int idx  = tid + i * 256;
        int row  = idx >> 4;
        int k    = (idx & 15) * 4;
        float4 v = make_float4(0.f, 0.f, 0.f, 0.f);
        if (base + row < NN)
            v = ((const float4*)X)[(base + row) * 16 + (k >> 2)];
        unsigned short h0, l0, h1, l1, h2v, l2v, h3, l3;
        split_bf16(v.x, h0, l0); split_bf16(v.y, h1, l1);
        split_bf16(v.z, h2v, l2v); split_bf16(v.w, h3, l3);
        unsigned long long hp = (unsigned long long)h0
            | ((unsigned long long)h1 << 16) | ((unsigned long long)h2v << 32)
            | ((unsigned long long)h3 << 48);
        unsigned long long lp = (unsigned long long)l0
            | ((unsigned long long)l1 << 16) | ((unsigned long long)l2v << 32)
            | ((unsigned long long)l3 << 48);
        uint32_t off = (uint32_t)(row * HSTR + k) * 2;
        *(unsigned long long*)(smem + G_AH + off) = hp;
        *(unsigned long long*)(smem + G_AL + off) = lp;
    }
    #pragma unroll
    for (int i = 0; i < 16; i++) {
        int idx = tid + i * 256;
        int k = idx >> 6, n = idx & 63;
        unsigned short h, l;
        split_bf16(W[idx], h, l);
        uint32_t off = (uint32_t)(n * HSTR + k) * 2;
        *(unsigned short*)(smem + G_BH + off) = h;
        *(unsigned short*)(smem + G_BL + off) = l;
    }
    __syncthreads();

    const int wid  = tid >> 5;
    const int lane = tid & 31;
    const uint32_t sb = smem_u32(smem);
    const int r0w = wid * 16;
    const int li  = lane >> 3;
    const int lw  = lane & 7;
    const uint32_t a_off =
        (uint32_t)(((r0w + (li & 1) * 8 + lw) * HSTR + (li >> 1) * 8) * 2);
    const uint32_t b_off =
        (uint32_t)((((li >> 1) * 8 + lw) * HSTR + (li & 1) * 8) * 2);

    float acc[8][4];
    #pragma unroll
    for (int nt = 0; nt < 8; nt++)
        #pragma unroll
        for (int q = 0; q < 4; q++) acc[nt][q] = 0.f;

    const uint32_t aB[3] = { sb + G_AH, sb + G_AH, sb + G_AL };
    const uint32_t bB[3] = { sb + G_BH, sb + G_BL, sb + G_BH };
    #pragma unroll
    for (int pass = 0; pass < 3; pass++) {
        #pragma unroll
        for (int kt = 0; kt < 4; kt++) {
            uint32_t a[4];
            ldsm4(a[0], a[1], a[2], a[3], aB[pass] + a_off + kt * 32);
            #pragma unroll
            for (int ntp = 0; ntp < 4; ntp++) {
                uint32_t b0, b1, b2, b3;
                ldsm4(b0, b1, b2, b3,
                      bB[pass] + b_off + (uint32_t)(ntp * 16 * HSTR * 2) + kt * 32);
                mma16816(acc[2 * ntp],     a, b0, b1);
                mma16816(acc[2 * ntp + 1], a, b2, b3);
            }
        }
    }

    const int rA = r0w + (lane >> 2);
    long long gA = base + rA, gB = gA + 8;
    bool vA = gA < NN, vB = gB < NN;
    #pragma unroll
    for (int nt = 0; nt < 8; nt++) {
        int cg = nt * 8 + (lane & 3) * 2;
        if (vA) *(__half2*)&Yh[gA * 64 + cg] = __floats2half2_rn(acc[nt][0], acc[nt][1]);
        if (vB) *(__half2*)&Yh[gB * 64 + cg] = __floats2half2_rn(acc[nt][2], acc[nt][3]);
    }
}

// ======================= Fused gather + GEMM (64-row tile) =================
static constexpr int F_AH = 0;
static constexpr int F_AL = F_AH + 64 * HSTR * 2;    // 9216
static constexpr int F_BH = F_AL + 64 * HSTR * 2;    // 18432
static constexpr int F_BL = F_BH + 64 * HSTR * 2;    // 27648
static constexpr int F_TOT = F_BL + 64 * HSTR * 2;   // 36864

// Gather layer activations for 64 nodes straight into smem bf16 planes, then
// multiply by W planes. Output: fp16 h to Hout, or fp32 (+bias_f) to Fout.
__global__ void __launch_bounds__(256) fused_gg(
        const uint4* __restrict__ Hin, const float* __restrict__ bias_g,
        const unsigned short* __restrict__ Wh, const unsigned short* __restrict__ Wl,
        __half* __restrict__ Hout, float* __restrict__ Fout,
        const float* __restrict__ bias_f) {
    extern __shared__ char smem[];
    const int tid  = threadIdx.x;
    const long long base = (long long)blockIdx.x * 64;

    // ---- phase 1: gather (4 threads per node, 16 cols each) ----
    {
        int node = (int)base + (tid >> 2);
        int sub  = tid & 3;
        unsigned short hs[16], ls[16];
        if (node < NN) {
            float dv = g_dinv[node];
            float a[16];
            {
                uint4 v0 = Hin[node * 8 + sub * 2];
                uint4 v1 = Hin[node * 8 + sub * 2 + 1];
                const __half2* p0 = (const __half2*)&v0;
                const __half2* p1 = (const __half2*)&v1;
                #pragma unroll
                for (int q = 0; q < 4; q++) {
                    float2 f0 = __half22float2(p0[q]);
                    float2 f1 = __half22float2(p1[q]);
                    a[2 * q]      = dv * f0.x;
                    a[2 * q + 1]  = dv * f0.y;
                    a[8 + 2 * q]     = dv * f1.x;
                    a[8 + 2 * q + 1] = dv * f1.y;
                }
            }
            int e   = g_off[node];
            int end = g_off[node + 1];
            for (; e + 1 < end; e += 2) {
                int s0 = __ldg(&g_csr[e]);
                int s1 = __ldg(&g_csr[e + 1]);
                float d0 = g_dinv[s0], d1 = g_dinv[s1];
                uint4 u0 = Hin[s0 * 8 + sub * 2];
                uint4 u1 = Hin[s0 * 8 + sub * 2 + 1];
                uint4 w0 = Hin[s1 * 8 + sub * 2];
                uint4 w1 = Hin[s1 * 8 + sub * 2 + 1];
                const __half2* q0 = (const __half2*)&u0;
                const __half2* q1 = (const __half2*)&u1;
                const __half2* r0 = (const __half2*)&w0;
                const __half2* r1 = (const __half2*)&w1;
                #pragma unroll
                for (int q = 0; q < 4; q++) {
                    float2 f0 = __half22float2(q0[q]);
                    float2 g0 = __half22float2(r0[q]);
                    a[2 * q]     = fmaf(d0, f0.x, fmaf(d1, g0.x, a[2 * q]));
                    a[2 * q + 1] = fmaf(d0, f0.y, fmaf(d1, g0.y, a[2 * q + 1]));
                    float2 f1 = __half22float2(q1[q]);
                    float2 g1 = __half22float2(r1[q]);
                    a[8 + 2 * q]     = fmaf(d0, f1.x, fmaf(d1, g1.x, a[8 + 2 * q]));
                    a[8 + 2 * q + 1] = fmaf(d0, f1.y, fmaf(d1, g1.y, a[8 + 2 * q + 1]));
                }
            }
            if (e < end) {
                int s0 = __ldg(&g_csr[e]);
                float d0 = g_dinv[s0];
                uint4 u0 = Hin[s0 * 8 + sub * 2];
                uint4 u1 = Hin[s0 * 8 + sub * 2 + 1];
                const __half2* q0 = (const __half2*)&u0;
                const __half2* q1 = (const __half2*)&u1;
                #pragma unroll
                for (int q = 0; q < 4; q++) {
                    float2 f0 = __half22float2(q0[q]);
                    a[2 * q]     = fmaf(d0, f0.x, a[2 * q]);
                    a[2 * q + 1] = fmaf(d0, f0.y, a[2 * q + 1]);
                    float2 f1 = __half22float2(q1[q]);
                    a[8 + 2 * q]     = fmaf(d0, f1.x, a[8 + 2 * q]);
                    a[8 + 2 * q + 1] = fmaf(d0, f1.y, a[8 + 2 * q + 1]);
                }
            }
            #pragma unroll
            for (int q = 0; q < 16; q++) {
                float o = fmaxf(fmaf(dv, a[q], bias_g[sub * 16 + q]), 0.f);
                split_bf16(o, hs[q], ls[q]);
            }
        } else {
            #pragma unroll
            for (int q = 0; q < 16; q++) { hs[q] = 0; ls[q] = 0; }
        }
        uint32_t off = (uint32_t)((tid >> 2) * HSTR + sub * 16) * 2;
        #pragma unroll
        for (int q = 0; q < 4; q++) {
            *(ushort4*)(smem + F_AH + off + q * 8) =
                make_ushort4(hs[4 * q], hs[4 * q + 1], hs[4 * q + 2], hs[4 * q + 3]);
            *(ushort4*)(smem + F_AL + off + q * 8) =
                make_ushort4(ls[4 * q], ls[4 * q + 1], ls[4 * q + 2], ls[4 * q + 3]);
        }
    }

    // ---- phase 2: B fill (pure copy of pre-split planes) ----
    #pragma unroll
    for (int i = 0; i < 2; i++) {
        int idx = tid + i * 256;               // uint4 index (512 total)
        int n = idx >> 3, k = (idx & 7) * 8;
        uint32_t off = (uint32_t)(n * HSTR + k) * 2;
        *(uint4*)(smem + F_BH + off) = ((const uint4*)Wh)[idx];
        *(uint4*)(smem + F_BL + off) = ((const uint4*)Wl)[idx];
    }
    __syncthreads();

    // ---- phase 3: mma (8 warps: 4 row-groups x 2 col-groups) ----
    const int wid  = tid >> 5;
    const int lane = tid & 31;
    const uint32_t sb = smem_u32(smem);
    const int rw = (wid & 3) * 16;
    const int cw = (wid >> 2) * 32;
    const int li = lane >> 3;
    const int lw = lane & 7;
    const uint32_t a_off =
        (uint32_t)(((rw + (li & 1) * 8 + lw) * HSTR + (li >> 1) * 8) * 2);
    const uint32_t b_off =
        (uint32_t)((((li >> 1) * 8 + lw) * HSTR + (li & 1) * 8) * 2);

    float acc[4][4];
    #pragma unroll
    for (int nt = 0; nt < 4; nt++)
        #pragma unroll
        for (int q = 0; q < 4; q++) acc[nt][q] = 0.f;

    const uint32_t aB[3] = { sb + F_AH, sb + F_AH, sb + F_AL };
    const uint32_t bB[3] = { sb + F_BH, sb + F_BL, sb + F_BH };
    #pragma unroll
    for (int pass = 0; pass < 3; pass++) {
        #pragma unroll
        for (int kt = 0; kt < 4; kt++) {
            uint32_t a[4];
            ldsm4(a[0], a[1], a[2], a[3], aB[pass] + a_off + kt * 32);
            #pragma unroll
            for (int ntp = 0; ntp < 2; ntp++) {
                uint32_t b0, b1, b2, b3;
                ldsm4(b0, b1, b2, b3,
                      bB[pass] + b_off + (uint32_t)((cw + ntp * 16) * HSTR * 2) + kt * 32);
                mma16816(acc[2 * ntp],     a, b0, b1);
                mma16816(acc[2 * ntp + 1], a, b2, b3);
            }
        }
    }

    // ---- epilogue ----
    const int rA = rw + (lane >> 2);
    long long gA = base + rA, gB = gA + 8;
    bool vA = gA < NN, vB = gB < NN;
    #pragma unroll
    for (int nt = 0; nt < 4; nt++) {
        int cg = cw + nt * 8 + (lane & 3) * 2;
        if (Hout) {
            if (vA) *(__half2*)&Hout[gA * 64 + cg] =
                __floats2half2_rn(acc[nt][0], acc[nt][1]);
            if (vB) *(__half2*)&Hout[gB * 64 + cg] =
                __floats2half2_rn(acc[nt][2], acc[nt][3]);
        } else {
            float bx = bias_f[cg], by = bias_f[cg + 1];
            if (vA) {
                float2 o = make_float2(acc[nt][0] + bx, acc[nt][1] + by);
                *(float2*)&Fout[gA * 64 + cg] = o;
            }
            if (vB) {
                float2 o = make_float2(acc[nt][2] + bx, acc[nt][3] + by);
                *(float2*)&Fout[gB * 64 + cg] = o;
            }
        }
    }
}

// ---------------------------------------------------------------------------
extern "C" void kernel_launch(void* const* d_in, const int* in_sizes, int n_in,
                              void* d_out, int out_size) {
    const float* x    = (const float*)d_in[0];
    const void*  ei   = d_in[1];
    const float* Ws   = (const float*)d_in[2];
    const float* bs   = (const float*)d_in[3];
    const float* Wout = (const float*)d_in[4];
    const float* bout = (const float*)d_in[5];
    float* out = (float*)d_out;

    uint4 *hA, *hB;
    unsigned short *wh, *wl;
    cudaGetSymbolAddress((void**)&hA, g_hA);
    cudaGetSymbolAddress((void**)&hB, g_hB);
    cudaGetSymbolAddress((void**)&wh, g_wh);
    cudaGetSymbolAddress((void**)&wl, g_wl);

    cudaFuncSetAttribute(gemm_f32, cudaFuncAttributeMaxDynamicSharedMemorySize, G_TOT);
    cudaFuncSetAttribute(fused_gg, cudaFuncAttributeMaxDynamicSharedMemorySize, F_TOT);

    // Side stream + events, created once on the (uncaptured) correctness call.
    static cudaStream_t s2 = nullptr;
    static cudaEvent_t  ev_fork = nullptr, ev_g1 = nullptr;
    if (!s2) {
        cudaStreamCreateWithFlags(&s2, cudaStreamNonBlocking);
        cudaEventCreateWithFlags(&ev_fork, cudaEventDisableTiming);
        cudaEventCreateWithFlags(&ev_g1, cudaEventDisableTiming);
    }

    const int GB_E  = (NE + 255) / 256;
    const int GB_N  = (NN + 255) / 256;
    const int GB_MM = (NN + 127) / 128;
    const int GB_F  = (NN + 63) / 64;

    // Fork: GEMM-1 (independent of the CSR build) runs on s2, writes hA.
    cudaEventRecord(ev_fork, 0);
    cudaStreamWaitEvent(s2, ev_fork, 0);
    gemm_f32<<<GB_MM, 256, G_TOT, s2>>>(x, Ws, (__half*)hA);
    cudaEventRecord(ev_g1, s2);

    // CSR build + weight-plane conversion on the main stream.
    degi_count<<<GB_E, 256>>>(ei);
    scan1<<<NSCB, SCAN_T>>>();
    scan23<<<GB_N, 256>>>();
    csr_fill<<<GB_E, 256>>>(ei);
    wconv<<<48, 256>>>(Ws, Wout);

    // Join, then 3 fused gather+gemm stages (ping-pong h buffers).
    cudaStreamWaitEvent(0, ev_g1, 0);
    fused_gg<<<GB_F, 256, F_TOT>>>(hA, bs,         wh,        wl,        (__half*)hB, nullptr, nullptr);
    fused_gg<<<GB_F, 256, F_TOT>>>(hB, bs + D,     wh + 4096, wl + 4096, (__half*)hA, nullptr, nullptr);
    fused_gg<<<GB_F, 256, F_TOT>>>(hA, bs + 2 * D, wh + 8192, wl + 8192, nullptr, out, bout);
}